// round 1
// baseline (speedup 1.0000x reference)
#include <cuda_runtime.h>
#include <cuda_bf16.h>

#define B_  1024
#define H_  128
#define NI  100000
#define T_  51200
#define NT  782   /* ceil(NI/128) */

// ---------------- device scratch (no allocations allowed) ----------------
__device__ float g_sum[3 * B_ * H_];
__device__ float g_cnt[3 * B_];
__device__ float g_user[B_ * H_];
__device__ float g_pm[B_ * NT];
__device__ float g_ps[B_ * NT];
__device__ float g_rowM[B_];
__device__ float g_rowInvS[B_];
__device__ float g_sumexpP[B_];

// ---------------- kernel 0: zero the accumulators -----------------------
__global__ void zero_kernel() {
    int i = blockIdx.x * blockDim.x + threadIdx.x;
    int stride = gridDim.x * blockDim.x;
    for (int j = i; j < 3 * B_ * H_; j += stride) g_sum[j] = 0.f;
    for (int j = i; j < 3 * B_;      j += stride) g_cnt[j] = 0.f;
    for (int j = i; j < B_;          j += stride) g_sumexpP[j] = 0.f;
}

// ---------------- kernel 1: segment-sum pooling (per table) -------------
// block = 512 threads = 4 tokens * 128 dims; grid = T/4
__global__ void pool_kernel(const int* __restrict__ idx,
                            const int* __restrict__ seg,
                            const float* __restrict__ table, int tbl) {
    int t = blockIdx.x * 4 + (threadIdx.x >> 7);
    int h = threadIdx.x & 127;
    int id = idx[t];
    int s  = seg[t];
    atomicAdd(&g_sum[(size_t)tbl * B_ * H_ + (size_t)s * H_ + h],
              table[(size_t)id * H_ + h]);
    if (h == 0) atomicAdd(&g_cnt[tbl * B_ + s], 1.0f);
}

// ---------------- kernel 2: build user vector ----------------------------
__global__ void user_kernel() {
    int i = blockIdx.x * blockDim.x + threadIdx.x;
    if (i >= B_ * H_) return;
    int b = i >> 7;
    float acc = 0.f;
#pragma unroll
    for (int t = 0; t < 3; t++) {
        float c = g_cnt[t * B_ + b];
        if (c > 0.f) acc += g_sum[t * B_ * H_ + i] / c;
    }
    g_user[i] = acc * (1.0f / 3.0f);
}

// ---------------- kernel 3: GEMM + fused per-tile softmax stats ----------
// 128x128 tile per CTA, 256 threads, 8x8 micro-tile using packed f32x2 FMA.
// Writes raw lin into d_out (staging) and per-(row, ntile) max / sumexp.
__global__ void __launch_bounds__(256)
gemm_kernel(const float* __restrict__ W, const float* __restrict__ bias,
            float* __restrict__ out) {
    extern __shared__ float sm[];
    float* As = sm;           // 128*128 floats (A tile, row-major [row][k])
    float* Bs = sm + 16384;   // 128*128 floats (B tile, [k][col])
    float* bs = sm + 32768;   // 128 floats (bias, later reused as row max)

    const int tx = threadIdx.x, ty = threadIdx.y;
    const int tid = ty * 16 + tx;
    const int nBase  = blockIdx.x * 128;
    const int rowBase = blockIdx.y * 128;

    // A tile is 128 contiguous rows of H=128 -> one contiguous 16384-float blob
    const float* Ag = g_user + (size_t)rowBase * H_;
    for (int i = tid; i < 16384; i += 256) As[i] = Ag[i];
    // B tile: Bs[k][c] = W[k][nBase + c], guarded
    for (int i = tid; i < 16384; i += 256) {
        int k = i >> 7, c = i & 127;
        int n = nBase + c;
        Bs[i] = (n < NI) ? W[(size_t)k * NI + n] : 0.0f;
    }
    if (tid < 128) {
        int n = nBase + tid;
        bs[tid] = (n < NI) ? bias[n] : 0.0f;
    }
    __syncthreads();

    unsigned long long acc[8][4];
#pragma unroll
    for (int i = 0; i < 8; i++)
#pragma unroll
        for (int j = 0; j < 4; j++) acc[i][j] = 0ull;

    const float* Arow0 = As + (size_t)ty * H_;   // rows ty + i*16
    const float* Bb    = Bs + tx * 2;            // col pairs (2tx, 2tx+1) + 32j

#pragma unroll 2
    for (int k = 0; k < 128; k++) {
        unsigned long long b2[4];
#pragma unroll
        for (int j = 0; j < 4; j++)
            b2[j] = *reinterpret_cast<const unsigned long long*>(Bb + k * 128 + j * 32);
#pragma unroll
        for (int i = 0; i < 8; i++) {
            float a = Arow0[i * 16 * 128 + k];
            unsigned long long a2;
            asm("mov.b64 %0, {%1, %1};" : "=l"(a2) : "f"(a));
#pragma unroll
            for (int j = 0; j < 4; j++)
                asm("fma.rn.f32x2 %0, %1, %2, %3;"
                    : "=l"(acc[i][j]) : "l"(a2), "l"(b2[j]), "l"(acc[i][j]));
        }
    }
    __syncthreads();   // everyone done reading As/Bs; reuse As region

    float* red = sm;   // 128 rows x 16 lanes reduction scratch

    // Phase A: add bias, store lin, per-thread row max
#pragma unroll
    for (int i = 0; i < 8; i++) {
        int row  = ty + i * 16;
        int rowG = rowBase + row;
        float m = -1e30f;
#pragma unroll
        for (int j = 0; j < 4; j++) {
            float lo, hi;
            asm("mov.b64 {%0, %1}, %2;" : "=f"(lo), "=f"(hi) : "l"(acc[i][j]));
            int c = tx * 2 + j * 32;
            lo += bs[c];
            hi += bs[c + 1];
            asm("mov.b64 %0, {%1, %2};" : "=l"(acc[i][j]) : "f"(lo), "f"(hi));
            int n = nBase + c;
            if (n + 1 < NI) {
                *reinterpret_cast<float2*>(out + (size_t)rowG * NI + n) =
                    make_float2(lo, hi);
                m = fmaxf(m, fmaxf(lo, hi));
            } else if (n < NI) {
                out[(size_t)rowG * NI + n] = lo;
                m = fmaxf(m, lo);
            }
        }
        red[row * 16 + tx] = m;
    }
    __syncthreads();
    if (tid < 128) {
        float m = -1e30f;
#pragma unroll
        for (int t = 0; t < 16; t++) m = fmaxf(m, red[tid * 16 + t]);
        bs[tid] = m;  // bias fully consumed; reuse as per-row tile max
    }
    __syncthreads();

    // Phase B: per-tile sumexp relative to tile row max
#pragma unroll
    for (int i = 0; i < 8; i++) {
        int row = ty + i * 16;
        float M = bs[row];
        float s = 0.f;
#pragma unroll
        for (int j = 0; j < 4; j++) {
            float lo, hi;
            asm("mov.b64 {%0, %1}, %2;" : "=f"(lo), "=f"(hi) : "l"(acc[i][j]));
            int n = nBase + tx * 2 + j * 32;
            if (n + 1 < NI)      s += __expf(lo - M) + __expf(hi - M);
            else if (n < NI)     s += __expf(lo - M);
        }
        red[row * 16 + tx] = s;
    }
    __syncthreads();
    if (tid < 128) {
        float s = 0.f;
#pragma unroll
        for (int t = 0; t < 16; t++) s += red[tid * 16 + t];
        int rowG = rowBase + tid;
        g_pm[(size_t)rowG * NT + blockIdx.x] = bs[tid];
        g_ps[(size_t)rowG * NT + blockIdx.x] = s;
    }
}

// ---------------- kernel 4: combine per-tile stats -> row M, 1/S ---------
__global__ void combine_kernel() {
    int b = blockIdx.x;
    int tid = threadIdx.x;
    __shared__ float sh[128];
    float m = -1e30f;
    for (int nt = tid; nt < NT; nt += 128)
        m = fmaxf(m, g_pm[(size_t)b * NT + nt]);
    sh[tid] = m; __syncthreads();
    for (int s = 64; s > 0; s >>= 1) {
        if (tid < s) sh[tid] = fmaxf(sh[tid], sh[tid + s]);
        __syncthreads();
    }
    float M = sh[0];
    __syncthreads();
    float sum = 0.f;
    for (int nt = tid; nt < NT; nt += 128)
        sum += g_ps[(size_t)b * NT + nt] * __expf(g_pm[(size_t)b * NT + nt] - M);
    sh[tid] = sum; __syncthreads();
    for (int s = 64; s > 0; s >>= 1) {
        if (tid < s) sh[tid] += sh[tid + s];
        __syncthreads();
    }
    if (tid == 0) { g_rowM[b] = M; g_rowInvS[b] = 1.0f / sh[0]; }
}

// ---------------- kernel 5: normalize lin -> probs, accumulate exp(probs)
// grid (25, B), block 256; each block covers 1024 float4 of one row
__global__ void norm_kernel(float* __restrict__ out) {
    int b = blockIdx.y;
    float M = g_rowM[b], inv = g_rowInvS[b];
    float4* row = reinterpret_cast<float4*>(out + (size_t)b * NI);
    int end = min(25000, (int)((blockIdx.x + 1) * 1024));
    float local = 0.f;
    for (int c = blockIdx.x * 1024 + threadIdx.x; c < end; c += 256) {
        float4 v = row[c];
        v.x = __expf(v.x - M) * inv;
        v.y = __expf(v.y - M) * inv;
        v.z = __expf(v.z - M) * inv;
        v.w = __expf(v.w - M) * inv;
        local += __expf(v.x) + __expf(v.y) + __expf(v.z) + __expf(v.w);
        row[c] = v;
    }
    __shared__ float sh[256];
    sh[threadIdx.x] = local; __syncthreads();
    for (int s = 128; s > 0; s >>= 1) {
        if (threadIdx.x < s) sh[threadIdx.x] += sh[threadIdx.x + s];
        __syncthreads();
    }
    if (threadIdx.x == 0) atomicAdd(&g_sumexpP[b], sh[0]);
}

// ---------------- kernel 6: labels passthrough + loss --------------------
__global__ void loss_kernel(const int* __restrict__ labels,
                            float* __restrict__ out) {
    int b = threadIdx.x;  // 1024 threads
    __shared__ float sh[1024];
    int lab = labels[b];
    float pl = out[(size_t)b * NI + lab];
    float lp = pl - logf(g_sumexpP[b]);   // log_softmax(probs)[b, lab]
    out[(size_t)B_ * NI + b] = (float)lab;
    sh[b] = lp; __syncthreads();
    for (int s = 512; s > 0; s >>= 1) {
        if (b < s) sh[b] += sh[b + s];
        __syncthreads();
    }
    if (b == 0) out[(size_t)B_ * NI + B_] = -sh[0] / (float)B_;
}

// -------------------------------------------------------------------------
extern "C" void kernel_launch(void* const* d_in, const int* in_sizes, int n_in,
                              void* d_out, int out_size) {
    const int*   item_idx     = (const int*)  d_in[0];
    const int*   item_seg     = (const int*)  d_in[1];
    const int*   entity_idx   = (const int*)  d_in[2];
    const int*   entity_seg   = (const int*)  d_in[3];
    const int*   word_idx     = (const int*)  d_in[4];
    const int*   word_seg     = (const int*)  d_in[5];
    const int*   labels       = (const int*)  d_in[6];
    const float* item_table   = (const float*)d_in[7];
    const float* entity_table = (const float*)d_in[8];
    const float* word_table   = (const float*)d_in[9];
    const float* rec_w        = (const float*)d_in[10];
    const float* rec_b        = (const float*)d_in[11];
    float* out = (float*)d_out;

    const int SMEM_BYTES = (16384 + 16384 + 128) * (int)sizeof(float); // 131584
    cudaFuncSetAttribute(gemm_kernel,
                         cudaFuncAttributeMaxDynamicSharedMemorySize, SMEM_BYTES);

    zero_kernel<<<256, 256>>>();
    pool_kernel<<<T_ / 4, 512>>>(item_idx,   item_seg,   item_table,   0);
    pool_kernel<<<T_ / 4, 512>>>(entity_idx, entity_seg, entity_table, 1);
    pool_kernel<<<T_ / 4, 512>>>(word_idx,   word_seg,   word_table,   2);
    user_kernel<<<(B_ * H_ + 255) / 256, 256>>>();
    gemm_kernel<<<dim3(NT, 8), dim3(16, 16), SMEM_BYTES>>>(rec_w, rec_b, out);
    combine_kernel<<<B_, 128>>>();
    norm_kernel<<<dim3(25, B_), 256>>>(out);
    loss_kernel<<<1, 1024>>>(labels, out);
}